// round 13
// baseline (speedup 1.0000x reference)
#include <cuda_runtime.h>
#include <cuda_bf16.h>
#include <cstdint>

// NnInteractionTokenizer: bond = x[row]*x[col]; local_field = segsum(bond, row);
// tokens = relu(relu([x, lf] @ w1^T + b1) @ w2^T + b2)
//
// local_field[r] = x[r] * sum_{e: row[e]=r} x[col[e]] -> edge phase only
// accumulates x[col[e]] into g_acc[row[e]]; x[r] multiply folds into node phase.
//
// R13 edge: hybrid gather. Each CTA stages x[0:STAGE] (104KB) in ITS OWN smem
// (no DSMEM remote reads — that was R8's failure). Persistent 296 CTAs x 1024
// thr, 2 CTAs/SM -> 64 warps/SM (100% occ kept). ~27% of random gathers become
// LDS (bank-degree ~4 cyc/warp) instead of divergent LDG (~32-line L1tex
// wavefront toll) -> cuts the dominant per-iteration cost at pipe saturation.
//
// Node: R7 exact form (measured 7.4us; TPN=2 regressed it) + PDL overlap.
// g_acc invariant: zeroed at module load; node re-zeroes g_acc[n] from the
// SAME thread that read it -> zero at entry of every graph replay.

#define N_NODES 100000
#define N_EDGES 6400000
#define TD 16
#define EPT 4
#define EBLK 1024
#define ECTAS 296                                   // 2 per SM
#define STAGE 26624                                 // floats staged: 104KB smem
#define SMEM_STAGE_BYTES (STAGE * 4)
#define CHUNK (EBLK * EPT)                          // 4096 edges
#define NCHUNKS ((N_EDGES + CHUNK - 1) / CHUNK)     // 1563

__device__ float g_acc[N_NODES];

// ---------------------------------------------------------------------------
// Edge phase. Dtype probe (uniform): reference asks int64 but JAX w/o x64
// yields int32 (confirmed: measured HBM traffic ~51MB). As uint32 words,
// int64 data (<2^17, LE) has odd words == 0; int32 data has random words ->
// P(8 specific odd words all zero) ~ 1e-40. All CTAs read the SAME 8 words.
// ---------------------------------------------------------------------------
__global__ void __launch_bounds__(EBLK, 2) edge_kernel(const void* __restrict__ ei,
                                                       const float* __restrict__ x) {
#if (__CUDACC_VER_MAJOR__ >= 12)
    cudaTriggerProgrammaticLaunchCompletion();
#endif
    extern __shared__ float sx[];          // x[0:STAGE]
    __shared__ int s_is64;

    const int t = threadIdx.x;

    // Stage the shared prefix of x (coalesced; L2-resident after first CTA).
    for (int i = t; i < STAGE; i += EBLK) sx[i] = x[i];

    if (t == 0) {
        const unsigned int* w = (const unsigned int*)ei;
        unsigned int acc = 0;
#pragma unroll
        for (int k = 0; k < 8; k++) acc |= w[2 * k + 1];
        s_is64 = (acc == 0u) ? 1 : 0;
    }
    __syncthreads();
    const int is64 = s_is64;

    for (int ch = blockIdx.x; ch < NCHUNKS; ch += ECTAS) {
        const long long base = (long long)ch * CHUNK + (long long)t * EPT;
        if (base >= N_EDGES) continue;

        int r0, r1, r2, r3, c0, c1, c2, c3;
        if (!is64) {
            const int4* row = (const int4*)ei;
            const int4* col = row + (N_EDGES / 4);
            int4 rv = __ldg(&row[base / 4]);
            int4 cv = __ldg(&col[base / 4]);
            r0 = rv.x; r1 = rv.y; r2 = rv.z; r3 = rv.w;
            c0 = cv.x; c1 = cv.y; c2 = cv.z; c3 = cv.w;
        } else {
            const longlong2* row = (const longlong2*)ei;
            const longlong2* col = row + (N_EDGES / 2);
            longlong2 ra = __ldg(&row[base / 2]);
            longlong2 rb = __ldg(&row[base / 2 + 1]);
            longlong2 ca = __ldg(&col[base / 2]);
            longlong2 cb = __ldg(&col[base / 2 + 1]);
            r0 = (int)ra.x; r1 = (int)ra.y; r2 = (int)rb.x; r3 = (int)rb.y;
            c0 = (int)ca.x; c1 = (int)ca.y; c2 = (int)cb.x; c3 = (int)cb.y;
        }

        // Hybrid gather: staged prefix via LDS (cheap banks), rest via LDG.
        float v0 = (c0 < STAGE) ? sx[c0] : __ldg(&x[c0]);
        float v1 = (c1 < STAGE) ? sx[c1] : __ldg(&x[c1]);
        float v2 = (c2 < STAGE) ? sx[c2] : __ldg(&x[c2]);
        float v3 = (c3 < STAGE) ? sx[c3] : __ldg(&x[c3]);

        atomicAdd(&g_acc[r0], v0);
        atomicAdd(&g_acc[r1], v1);
        atomicAdd(&g_acc[r2], v2);
        atomicAdd(&g_acc[r3], v3);
    }
}

// ---------------------------------------------------------------------------
// Node phase (R7 exact form, measured 7.4us): 1 thread/node; x load + weight
// staging BEFORE the PDL sync (overlaps edge tail); same-thread g_acc
// read->clear; LDS.128 layer-2 weights.
// ---------------------------------------------------------------------------
__global__ void __launch_bounds__(256) node_kernel(const float* __restrict__ x,
                                                   const float* __restrict__ w1,
                                                   const float* __restrict__ b1,
                                                   const float* __restrict__ w2,
                                                   const float* __restrict__ b2,
                                                   float* __restrict__ out) {
    __shared__ float sw1[2 * TD];
    __shared__ float sb1[TD];
    __shared__ __align__(16) float sw2[TD * TD];
    __shared__ float sb2[TD];

    const int t = threadIdx.x;
    const int n = blockIdx.x * 256 + t;
    const bool act = (n < N_NODES);

    // Prologue (no g_acc access) — overlaps edge tail under PDL.
    float s = 0.f;
    if (act) s = x[n];
    if (t < 2 * TD) sw1[t] = w1[t];
    if (t < TD) { sb1[t] = b1[t]; sb2[t] = b2[t]; }
    sw2[t] = w2[t];   // blockDim == 256 == TD*TD
    __syncthreads();

#if (__CUDACC_VER_MAJOR__ >= 12)
    cudaGridDependencySynchronize();   // edge grid fully complete
#endif

    float lfa = 0.f;
    if (act) lfa = g_acc[n];
    if (act) g_acc[n] = 0.0f;   // same thread, same address: ordered after read

    const float lf = s * lfa;

    float h[TD];
#pragma unroll
    for (int j = 0; j < TD; j++) {
        float v = fmaf(sw1[2 * j + 1], lf, fmaf(sw1[2 * j], s, sb1[j]));
        h[j] = v > 0.f ? v : 0.f;
    }

    float4* o = (float4*)(out + (size_t)n * TD);
#pragma unroll
    for (int k4 = 0; k4 < 4; k4++) {
        float4 res;
        float* rp = (float*)&res;
#pragma unroll
        for (int kk = 0; kk < 4; kk++) {
            const int k = k4 * 4 + kk;
            float v = sb2[k];
            const float4* wrow = (const float4*)&sw2[k * TD];
#pragma unroll
            for (int j4 = 0; j4 < 4; j4++) {
                float4 w = wrow[j4];
                v = fmaf(w.x, h[j4 * 4 + 0], v);
                v = fmaf(w.y, h[j4 * 4 + 1], v);
                v = fmaf(w.z, h[j4 * 4 + 2], v);
                v = fmaf(w.w, h[j4 * 4 + 3], v);
            }
            rp[kk] = v > 0.f ? v : 0.f;
        }
        if (act) o[k4] = res;
    }
}

extern "C" void kernel_launch(void* const* d_in, const int* in_sizes, int n_in,
                              void* d_out, int out_size) {
    const float* x  = (const float*)d_in[0];
    const void*  ei = d_in[1];
    const float* w1 = (const float*)d_in[2];
    const float* b1 = (const float*)d_in[3];
    const float* w2 = (const float*)d_in[4];
    const float* b2 = (const float*)d_in[5];
    float* out = (float*)d_out;

    // Idempotent, deterministic, not a stream op (capture-legal).
    cudaFuncSetAttribute(edge_kernel,
                         cudaFuncAttributeMaxDynamicSharedMemorySize,
                         SMEM_STAGE_BYTES);

    edge_kernel<<<ECTAS, EBLK, SMEM_STAGE_BYTES>>>(ei, x);

    cudaLaunchConfig_t cfg = {};
    cfg.gridDim  = dim3((N_NODES + 255) / 256, 1, 1);
    cfg.blockDim = dim3(256, 1, 1);
    cudaLaunchAttribute attr[1];
    attr[0].id = cudaLaunchAttributeProgrammaticStreamSerialization;
    attr[0].val.programmaticStreamSerializationAllowed = 1;
    cfg.attrs = attr;
    cfg.numAttrs = 1;
    cudaLaunchKernelEx(&cfg, node_kernel, x, w1, b1, w2, b2, out);
}

// round 14
// speedup vs baseline: 1.6442x; 1.6442x over previous
#include <cuda_runtime.h>
#include <cuda_bf16.h>
#include <cstdint>

// NnInteractionTokenizer: bond = x[row]*x[col]; local_field = segsum(bond, row);
// tokens = relu(relu([x, lf] @ w1^T + b1) @ w2^T + b2)
//
// local_field[r] = x[r] * sum_{e: row[e]=r} x[col[e]] -> edge phase only
// accumulates x[col[e]] into g_acc[row[e]]; x[r] multiply folds into node phase.
//
// R14 = assembly of measured winners:
//   edge: R11 exact (256thr x 8 CTA/SM = 64 warps, batched int4 index loads,
//         batched divergent gathers, 4x REDG.F32) — measured ~50us floor.
//         R13's hybrid smem gather broke the load batching and regressed 1.7x;
//         do not disturb this loop.
//   node: R7 exact (1 thread/node, loads before weight barrier, same-thread
//         g_acc read->clear, LDS.128 weights) — measured 7.4us.
//   PDL: node prologue overlaps edge tail (R12: ~1.2us recovered).
//
// g_acc invariant: __device__ globals start zeroed; node re-zeroes g_acc[n]
// from the SAME thread that read it -> zero at entry of every graph replay.

#define N_NODES 100000
#define N_EDGES 6400000
#define TD 16
#define EPT 4

__device__ float g_acc[N_NODES];

// ---------------------------------------------------------------------------
// Edge phase: EPT edges/thread; vectorized index loads (DRAM stream), batched
// divergent gathers (L1/L2), EPT fire-and-forget REDG.F32 into g_acc.
//
// Dtype probe (per block, uniform): reference asks int64 but JAX w/o x64
// yields int32 (confirmed: measured HBM traffic ~51MB). As uint32 words,
// int64 data (<2^17, LE) has odd words == 0; int32 data has random words ->
// P(8 specific odd words all zero) ~ 1e-40. All blocks read the SAME 8 words
// (L2 broadcast) -> globally uniform decision.
// ---------------------------------------------------------------------------
__global__ void __launch_bounds__(256, 8) edge_kernel(const void* __restrict__ ei,
                                                      const float* __restrict__ x) {
#if (__CUDACC_VER_MAJOR__ >= 12)
    cudaTriggerProgrammaticLaunchCompletion();   // fires when last wave is resident
#endif
    __shared__ int s_is64;
    if (threadIdx.x == 0) {
        const unsigned int* w = (const unsigned int*)ei;
        unsigned int acc = 0;
#pragma unroll
        for (int k = 0; k < 8; k++) acc |= w[2 * k + 1];
        s_is64 = (acc == 0u) ? 1 : 0;
    }
    __syncthreads();

    const int tid = blockIdx.x * blockDim.x + threadIdx.x;
    const long long base = (long long)tid * EPT;
    if (base >= N_EDGES) return;

    if (!s_is64) {
        // int32 path (the measured-real one): kept lean for <=32 regs.
        const int4* row = (const int4*)ei;
        const int4* col = row + (N_EDGES / 4);
        int4 rv = __ldg(&row[base / 4]);
        int4 cv = __ldg(&col[base / 4]);

        float v0 = __ldg(&x[cv.x]);
        float v1 = __ldg(&x[cv.y]);
        float v2 = __ldg(&x[cv.z]);
        float v3 = __ldg(&x[cv.w]);

        atomicAdd(&g_acc[rv.x], v0);
        atomicAdd(&g_acc[rv.y], v1);
        atomicAdd(&g_acc[rv.z], v2);
        atomicAdd(&g_acc[rv.w], v3);
    } else {
        const longlong2* row = (const longlong2*)ei;          // edge_index[0]
        const longlong2* col = row + (N_EDGES / 2);           // edge_index[1]
        longlong2 r0 = __ldg(&row[base / 2]);
        longlong2 r1 = __ldg(&row[base / 2 + 1]);
        longlong2 c0 = __ldg(&col[base / 2]);
        longlong2 c1 = __ldg(&col[base / 2 + 1]);

        float v0 = __ldg(&x[(int)c0.x]);
        float v1 = __ldg(&x[(int)c0.y]);
        float v2 = __ldg(&x[(int)c1.x]);
        float v3 = __ldg(&x[(int)c1.y]);

        atomicAdd(&g_acc[(int)r0.x], v0);
        atomicAdd(&g_acc[(int)r0.y], v1);
        atomicAdd(&g_acc[(int)r1.x], v2);
        atomicAdd(&g_acc[(int)r1.y], v3);
    }
}

// ---------------------------------------------------------------------------
// Node phase (R7 exact logic): 1 thread/node; x load + weight staging BEFORE
// the PDL sync (overlaps edge tail); same-thread g_acc read->clear; LDS.128
// layer-2 weights; coalesced STG.128 output.
// ---------------------------------------------------------------------------
__global__ void __launch_bounds__(256) node_kernel(const float* __restrict__ x,
                                                   const float* __restrict__ w1,
                                                   const float* __restrict__ b1,
                                                   const float* __restrict__ w2,
                                                   const float* __restrict__ b2,
                                                   float* __restrict__ out) {
    __shared__ float sw1[2 * TD];
    __shared__ float sb1[TD];
    __shared__ __align__(16) float sw2[TD * TD];
    __shared__ float sb2[TD];

    const int t = threadIdx.x;
    const int n = blockIdx.x * 256 + t;
    const bool act = (n < N_NODES);

    // Prologue (no g_acc access) — overlaps edge tail under PDL.
    float s = 0.f;
    if (act) s = x[n];
    if (t < 2 * TD) sw1[t] = w1[t];
    if (t < TD) { sb1[t] = b1[t]; sb2[t] = b2[t]; }
    sw2[t] = w2[t];   // blockDim == 256 == TD*TD
    __syncthreads();

#if (__CUDACC_VER_MAJOR__ >= 12)
    cudaGridDependencySynchronize();   // edge grid fully complete
#endif

    float lfa = 0.f;
    if (act) lfa = g_acc[n];
    if (act) g_acc[n] = 0.0f;   // same thread, same address: ordered after read

    const float lf = s * lfa;

    float h[TD];
#pragma unroll
    for (int j = 0; j < TD; j++) {
        float v = fmaf(sw1[2 * j + 1], lf, fmaf(sw1[2 * j], s, sb1[j]));
        h[j] = v > 0.f ? v : 0.f;
    }

    float4* o = (float4*)(out + (size_t)n * TD);
#pragma unroll
    for (int k4 = 0; k4 < 4; k4++) {
        float4 res;
        float* rp = (float*)&res;
#pragma unroll
        for (int kk = 0; kk < 4; kk++) {
            const int k = k4 * 4 + kk;
            float v = sb2[k];
            const float4* wrow = (const float4*)&sw2[k * TD];
#pragma unroll
            for (int j4 = 0; j4 < 4; j4++) {
                float4 w = wrow[j4];
                v = fmaf(w.x, h[j4 * 4 + 0], v);
                v = fmaf(w.y, h[j4 * 4 + 1], v);
                v = fmaf(w.z, h[j4 * 4 + 2], v);
                v = fmaf(w.w, h[j4 * 4 + 3], v);
            }
            rp[kk] = v > 0.f ? v : 0.f;
        }
        if (act) o[k4] = res;
    }
}

extern "C" void kernel_launch(void* const* d_in, const int* in_sizes, int n_in,
                              void* d_out, int out_size) {
    const float* x  = (const float*)d_in[0];
    const void*  ei = d_in[1];
    const float* w1 = (const float*)d_in[2];
    const float* b1 = (const float*)d_in[3];
    const float* w2 = (const float*)d_in[4];
    const float* b2 = (const float*)d_in[5];
    float* out = (float*)d_out;

    edge_kernel<<<N_EDGES / EPT / 256, 256>>>(ei, x);

    // Node launch with PDL attribute (overlap prologue with edge tail).
    cudaLaunchConfig_t cfg = {};
    cfg.gridDim  = dim3((N_NODES + 255) / 256, 1, 1);
    cfg.blockDim = dim3(256, 1, 1);
    cudaLaunchAttribute attr[1];
    attr[0].id = cudaLaunchAttributeProgrammaticStreamSerialization;
    attr[0].val.programmaticStreamSerializationAllowed = 1;
    cfg.attrs = attr;
    cfg.numAttrs = 1;
    cudaLaunchKernelEx(&cfg, node_kernel, x, w1, b1, w2, b2, out);
}